// round 3
// baseline (speedup 1.0000x reference)
#include <cuda_runtime.h>

#define BATCH 8
#define SEQ   4096
#define DIM   256
#define SPLITK 4
#define SCHUNK (SEQ/SPLITK)   // 1024
#define KT 32

// Scratch (no allocs allowed -> __device__ globals)
__device__ float g_KVp[SPLITK*BATCH*DIM*DIM];  // split-K partials [sp][b][d][e]  (8 MB)
__device__ float g_KV [BATCH*DIM*DIM];         // KV = phiK^T V   [b][d][e]       (2 MB)
__device__ float g_ksp[BATCH*16*DIM];          // k_sum partials
__device__ float g_ks [BATCH*DIM];             // k_sum[b][d]
__device__ float g_bot[BATCH*SEQ];             // normalizer bottom[b][s]

__device__ __forceinline__ float phi(float x){
    // sigmoid(0.6053*x - 4.102) = 1/(1+exp(4.102 - 0.6053*x))
    return 1.0f / (1.0f + __expf(4.102f - 0.6053f * x));
}

// ---------------------------------------------------------------------------
// k_sum[b][d] = sum_s phi(K[b][s][d])  -- two-stage, deterministic
// ---------------------------------------------------------------------------
__global__ __launch_bounds__(256) void ksum_part_kernel(const float* __restrict__ K){
    int b = blockIdx.y, sc = blockIdx.x, d = threadIdx.x;
    const float* Kp = K + ((size_t)b*SEQ + (size_t)sc*(SEQ/16))*DIM + d;
    float acc = 0.f;
    #pragma unroll 4
    for (int s = 0; s < SEQ/16; s++) acc += phi(Kp[(size_t)s*DIM]);
    g_ksp[(b*16 + sc)*DIM + d] = acc;
}

__global__ __launch_bounds__(256) void ksum_reduce_kernel(){
    int i = blockIdx.x*256 + threadIdx.x;      // [0, BATCH*DIM)
    int b = i / DIM, d = i % DIM;
    float acc = 0.f;
    #pragma unroll
    for (int sc = 0; sc < 16; sc++) acc += g_ksp[(b*16 + sc)*DIM + d];
    g_ks[i] = acc;
}

// ---------------------------------------------------------------------------
// GEMM 1 (split-K): KVp[sp][b][d][e] = sum_{s in chunk} phi(K[b][s][d]) * V[b][s][e]
// 64x64 tile, 256 threads, 4x4 microtile
// ---------------------------------------------------------------------------
__global__ __launch_bounds__(256) void kv_part_kernel(const float* __restrict__ K,
                                                      const float* __restrict__ V){
    __shared__ float As[KT][64];   // phi(K) tile: [s][d]  (K-dim = s, contiguous loads)
    __shared__ float Bs[KT][64];   // V tile:      [s][e]
    int b  = blockIdx.z;
    int sp = blockIdx.y;
    int dt = blockIdx.x >> 2;      // d-tile 0..3
    int et = blockIdx.x & 3;       // e-tile 0..3
    int t  = threadIdx.x;
    int tx = t & 15, ty = t >> 4;

    const float* Kbase = K + (size_t)b*SEQ*DIM + (size_t)sp*SCHUNK*DIM + dt*64;
    const float* Vbase = V + (size_t)b*SEQ*DIM + (size_t)sp*SCHUNK*DIM + et*64;

    float acc[4][4] = {};
    for (int k0 = 0; k0 < SCHUNK; k0 += KT){
        #pragma unroll
        for (int j = 0; j < 8; j++){
            int idx = t + j*256;
            int row = idx >> 6, col = idx & 63;
            As[row][col] = phi(Kbase[(size_t)(k0+row)*DIM + col]);
            Bs[row][col] =     Vbase[(size_t)(k0+row)*DIM + col];
        }
        __syncthreads();
        #pragma unroll
        for (int kk = 0; kk < KT; kk++){
            float4 a  = *(const float4*)&As[kk][ty*4];
            float4 bv = *(const float4*)&Bs[kk][tx*4];
            float av[4] = {a.x, a.y, a.z, a.w};
            float bb[4] = {bv.x, bv.y, bv.z, bv.w};
            #pragma unroll
            for (int i = 0; i < 4; i++)
                #pragma unroll
                for (int j = 0; j < 4; j++)
                    acc[i][j] += av[i] * bb[j];
        }
        __syncthreads();
    }
    float* out = g_KVp + (((size_t)sp*BATCH + b)*DIM + dt*64 + ty*4)*DIM + et*64 + tx*4;
    #pragma unroll
    for (int i = 0; i < 4; i++){
        float4 v4 = {acc[i][0], acc[i][1], acc[i][2], acc[i][3]};
        *(float4*)(out + (size_t)i*DIM) = v4;
    }
}

__global__ __launch_bounds__(256) void kv_reduce_kernel(){
    int i = blockIdx.x*256 + threadIdx.x;      // [0, BATCH*DIM*DIM)
    float acc = 0.f;
    #pragma unroll
    for (int s = 0; s < SPLITK; s++) acc += g_KVp[(size_t)s*BATCH*DIM*DIM + i];
    g_KV[i] = acc;
}

// ---------------------------------------------------------------------------
// bottom[b][s] = sum_d phi(Q[b][s][d]) * k_sum[b][d]   (one warp per row)
// ---------------------------------------------------------------------------
__global__ __launch_bounds__(256) void bottom_kernel(const float* __restrict__ Q){
    int warp = threadIdx.x >> 5, lane = threadIdx.x & 31;
    int row = blockIdx.x*8 + warp;             // [0, BATCH*SEQ)
    int b = row >> 12;                         // /SEQ
    const float* Qp = Q + (size_t)row*DIM;
    const float* ks = g_ks + b*DIM;
    float acc = 0.f;
    #pragma unroll
    for (int j = 0; j < 8; j++){
        int d = lane + j*32;
        acc += phi(Qp[d]) * ks[d];
    }
    #pragma unroll
    for (int o = 16; o > 0; o >>= 1) acc += __shfl_xor_sync(0xffffffffu, acc, o);
    if (lane == 0) g_bot[row] = acc;
}

// ---------------------------------------------------------------------------
// GEMM 2: Out[b][s][e] = (sum_d phi(Q[b][s][d]) * KV[b][d][e]) / bottom[b][s]
// 64x64 tile, K-dim = d (contiguous) -> transposed A store with pad=68
// ---------------------------------------------------------------------------
__global__ __launch_bounds__(256) void out_kernel(const float* __restrict__ Q,
                                                  float* __restrict__ Out){
    __shared__ float As[KT][68];   // phi(Q) transposed: [d][s], pad keeps 16B align
    __shared__ float Bs[KT][64];   // KV tile: [d][e]
    __shared__ float invb[64];
    int b  = blockIdx.z;
    int st = blockIdx.y;           // s-tile 0..63
    int et = blockIdx.x;           // e-tile 0..3
    int t  = threadIdx.x;
    int tx = t & 15, ty = t >> 4;

    const float* Qbase = Q + ((size_t)b*SEQ + st*64)*DIM;
    const float* KVb   = g_KV + (size_t)b*DIM*DIM + et*64;

    if (t < 64) invb[t] = 1.0f / g_bot[b*SEQ + st*64 + t];

    float acc[4][4] = {};
    for (int k0 = 0; k0 < DIM; k0 += KT){
        #pragma unroll
        for (int j = 0; j < 8; j++){
            int idx = t + j*256;
            int kk = idx & 31, ss = idx >> 5;
            As[kk][ss] = phi(Qbase[(size_t)ss*DIM + k0 + kk]);
        }
        #pragma unroll
        for (int j = 0; j < 8; j++){
            int idx = t + j*256;
            int kk = idx >> 6, ee = idx & 63;
            Bs[kk][ee] = KVb[(size_t)(k0+kk)*DIM + ee];
        }
        __syncthreads();
        #pragma unroll
        for (int kk = 0; kk < KT; kk++){
            float4 a  = *(const float4*)&As[kk][ty*4];
            float4 bv = *(const float4*)&Bs[kk][tx*4];
            float av[4] = {a.x, a.y, a.z, a.w};
            float bb[4] = {bv.x, bv.y, bv.z, bv.w};
            #pragma unroll
            for (int i = 0; i < 4; i++)
                #pragma unroll
                for (int j = 0; j < 4; j++)
                    acc[i][j] += av[i] * bb[j];
        }
        __syncthreads();
    }
    #pragma unroll
    for (int i = 0; i < 4; i++){
        float ib = invb[ty*4 + i];
        float4 v4 = {acc[i][0]*ib, acc[i][1]*ib, acc[i][2]*ib, acc[i][3]*ib};
        *(float4*)(Out + ((size_t)b*SEQ + st*64 + ty*4 + i)*DIM + et*64 + tx*4) = v4;
    }
}

// ---------------------------------------------------------------------------
extern "C" void kernel_launch(void* const* d_in, const int* in_sizes, int n_in,
                              void* d_out, int out_size){
    const float* Q = (const float*)d_in[0];
    const float* K = (const float*)d_in[1];
    const float* V = (const float*)d_in[2];
    float* Out = (float*)d_out;

    ksum_part_kernel  <<<dim3(16, 8), 256>>>(K);
    ksum_reduce_kernel<<<(BATCH*DIM)/256, 256>>>();
    kv_part_kernel    <<<dim3(16, SPLITK, BATCH), 256>>>(K, V);
    kv_reduce_kernel  <<<(BATCH*DIM*DIM)/256, 256>>>();
    bottom_kernel     <<<(BATCH*SEQ)/8, 256>>>(Q);
    out_kernel        <<<dim3(4, 64, BATCH), 256>>>(Q, Out);
}

// round 4
// speedup vs baseline: 2.4510x; 2.4510x over previous
#include <cuda_runtime.h>
#include <cstdint>

#define BATCH 8
#define SEQ   4096
#define DIM   256
#define SPLITK 8
#define SCHUNK (SEQ/SPLITK)   // 512

// Scratch (no allocs allowed -> __device__ globals)
__device__ float g_KVp[SPLITK*BATCH*DIM*DIM];  // split-K partials [sp][b][d][e]  (16.8 MB)
__device__ float g_KV [BATCH*DIM*DIM];         // KV = phiK^T V   [b][d][e]
__device__ float g_ksp[BATCH*16*DIM];          // k_sum partials
__device__ float g_ks [BATCH*DIM];             // k_sum[b][d]
__device__ float g_bot[BATCH*SEQ];             // normalizer bottom[b][s]

__device__ __forceinline__ float phi(float x){
    // sigmoid(0.6053*x - 4.102) = 1/(1+exp(4.102 - 0.6053*x))
    return 1.0f / (1.0f + __expf(4.102f - 0.6053f * x));
}
__device__ __forceinline__ uint32_t to_tf32(float x){
    uint32_t r; asm("cvt.rna.tf32.f32 %0, %1;" : "=r"(r) : "f"(x)); return r;
}
__device__ __forceinline__ void mma8(float c[4], const uint32_t a[4],
                                     uint32_t b0, uint32_t b1){
    asm volatile("mma.sync.aligned.m16n8k8.row.col.f32.tf32.tf32.f32 "
        "{%0,%1,%2,%3},{%4,%5,%6,%7},{%8,%9},{%0,%1,%2,%3};"
        : "+f"(c[0]),"+f"(c[1]),"+f"(c[2]),"+f"(c[3])
        : "r"(a[0]),"r"(a[1]),"r"(a[2]),"r"(a[3]),"r"(b0),"r"(b1));
}

// ---------------------------------------------------------------------------
// k_sum[b][d] = sum_s phi(K[b][s][d])  -- two-stage, deterministic
// ---------------------------------------------------------------------------
__global__ __launch_bounds__(256) void ksum_part_kernel(const float* __restrict__ K){
    int b = blockIdx.y, sc = blockIdx.x, d = threadIdx.x;
    const float* Kp = K + ((size_t)b*SEQ + (size_t)sc*(SEQ/16))*DIM + d;
    float acc = 0.f;
    #pragma unroll 4
    for (int s = 0; s < SEQ/16; s++) acc += phi(Kp[(size_t)s*DIM]);
    g_ksp[(b*16 + sc)*DIM + d] = acc;
}
__global__ __launch_bounds__(256) void ksum_reduce_kernel(){
    int i = blockIdx.x*256 + threadIdx.x;      // [0, BATCH*DIM)
    int b = i / DIM, d = i % DIM;
    float acc = 0.f;
    #pragma unroll
    for (int sc = 0; sc < 16; sc++) acc += g_ksp[(b*16 + sc)*DIM + d];
    g_ks[i] = acc;
}

// ---------------------------------------------------------------------------
// GEMM 1 (tf32 mma, split-K): KVp[sp][b][d][e] += phi(K[b][s][d]) * V[b][s][e]
// 128x128 tile, 8 warps (2m x 4n) of 64x32, k-chunk 32 (s-dim)
// A = phi(K) in SMEM as [k][m] (natural: K rows are k-slices), stride 136
// B = V      in SMEM as [k][n], stride 136. Fragment reads conflict-free.
// ---------------------------------------------------------------------------
__global__ __launch_bounds__(256) void kv_part_kernel(const float* __restrict__ K,
                                                      const float* __restrict__ V){
    __shared__ uint32_t As[32][136];
    __shared__ uint32_t Bs[32][136];
    int b  = blockIdx.z, sp = blockIdx.y;
    int dt = blockIdx.x >> 1, et = blockIdx.x & 1;   // 2x2 tiles of 128
    int t = threadIdx.x, lane = t & 31, w = t >> 5;
    int wm = (w & 1)*64, wn = (w >> 1)*32;
    int gid = lane >> 2, tig = lane & 3;

    const float* Kb = K + ((size_t)b*SEQ + (size_t)sp*SCHUNK)*DIM + dt*128;
    const float* Vb = V + ((size_t)b*SEQ + (size_t)sp*SCHUNK)*DIM + et*128;

    float acc[4][4][4] = {};
    int lr = t >> 5, lc = (t & 31)*4;                // loader: 8 rows/pass, 32 float4/row
    for (int k0 = 0; k0 < SCHUNK; k0 += 32){
        #pragma unroll
        for (int p = 0; p < 4; p++){
            int row = lr + p*8;
            float4 k4 = *(const float4*)(Kb + (size_t)(k0+row)*DIM + lc);
            float4 v4 = *(const float4*)(Vb + (size_t)(k0+row)*DIM + lc);
            uint4 ka = { to_tf32(phi(k4.x)), to_tf32(phi(k4.y)),
                         to_tf32(phi(k4.z)), to_tf32(phi(k4.w)) };
            uint4 va = { to_tf32(v4.x), to_tf32(v4.y), to_tf32(v4.z), to_tf32(v4.w) };
            *(uint4*)&As[row][lc] = ka;
            *(uint4*)&Bs[row][lc] = va;
        }
        __syncthreads();
        #pragma unroll
        for (int kk = 0; kk < 32; kk += 8){
            uint32_t af[4][4];
            #pragma unroll
            for (int mi = 0; mi < 4; mi++){
                int m = wm + mi*16;
                af[mi][0] = As[kk+tig  ][m+gid  ];
                af[mi][1] = As[kk+tig  ][m+gid+8];
                af[mi][2] = As[kk+tig+4][m+gid  ];
                af[mi][3] = As[kk+tig+4][m+gid+8];
            }
            #pragma unroll
            for (int ni = 0; ni < 4; ni++){
                int n = wn + ni*8;
                uint32_t b0 = Bs[kk+tig  ][n+gid];
                uint32_t b1 = Bs[kk+tig+4][n+gid];
                #pragma unroll
                for (int mi = 0; mi < 4; mi++) mma8(acc[mi][ni], af[mi], b0, b1);
            }
        }
        __syncthreads();
    }
    float* outp = g_KVp + (((size_t)sp*BATCH + b)*DIM + dt*128)*DIM + et*128;
    #pragma unroll
    for (int mi = 0; mi < 4; mi++)
        #pragma unroll
        for (int ni = 0; ni < 4; ni++){
            int r = wm + mi*16 + gid, c = wn + ni*8 + tig*2;
            float2 v0 = {acc[mi][ni][0], acc[mi][ni][1]};
            float2 v1 = {acc[mi][ni][2], acc[mi][ni][3]};
            *(float2*)(outp + (size_t)r*DIM + c)     = v0;
            *(float2*)(outp + (size_t)(r+8)*DIM + c) = v1;
        }
}

__global__ __launch_bounds__(256) void kv_reduce_kernel(){
    int i = (blockIdx.x*256 + threadIdx.x)*4;  // float4 over BATCH*DIM*DIM
    float4 acc = {0.f,0.f,0.f,0.f};
    #pragma unroll
    for (int s = 0; s < SPLITK; s++){
        float4 v = *(const float4*)&g_KVp[(size_t)s*BATCH*DIM*DIM + i];
        acc.x += v.x; acc.y += v.y; acc.z += v.z; acc.w += v.w;
    }
    *(float4*)&g_KV[i] = acc;
}

// ---------------------------------------------------------------------------
// bottom[b][s] = sum_d phi(Q[b][s][d]) * k_sum[b][d]   (one warp per row)
// ---------------------------------------------------------------------------
__global__ __launch_bounds__(256) void bottom_kernel(const float* __restrict__ Q){
    int warp = threadIdx.x >> 5, lane = threadIdx.x & 31;
    int row = blockIdx.x*8 + warp;             // [0, BATCH*SEQ)
    int b = row >> 12;
    const float* Qp = Q + (size_t)row*DIM;
    const float* ks = g_ks + b*DIM;
    float acc = 0.f;
    #pragma unroll
    for (int j = 0; j < 8; j++){
        int d = lane + j*32;
        acc += phi(Qp[d]) * ks[d];
    }
    #pragma unroll
    for (int o = 16; o > 0; o >>= 1) acc += __shfl_xor_sync(0xffffffffu, acc, o);
    if (lane == 0) g_bot[row] = acc;
}

// ---------------------------------------------------------------------------
// GEMM 2 (tf32 mma): Out[b][s][e] = (phi(Q[b][s][:]) . KV[b][:][e]) / bottom[b][s]
// 128x128 tile, 8 warps 64x32, k-chunk 32 (d-dim)
// A = phi(Q) in SMEM as [m][k] natural row-major, stride 36 (reads 4*gid+tig: CF)
// B = KV     in SMEM as [k][n], stride 136
// ---------------------------------------------------------------------------
__global__ __launch_bounds__(256) void out_kernel(const float* __restrict__ Q,
                                                  float* __restrict__ Out){
    __shared__ uint32_t As[128][36];
    __shared__ uint32_t Bs[32][136];
    __shared__ float invb[128];
    int b = blockIdx.z, st = blockIdx.y, et = blockIdx.x;
    int t = threadIdx.x, lane = t & 31, w = t >> 5;
    int wm = (w & 1)*64, wn = (w >> 1)*32;
    int gid = lane >> 2, tig = lane & 3;

    const float* Qb  = Q + ((size_t)b*SEQ + st*128)*DIM;
    const float* KVb = g_KV + (size_t)b*DIM*DIM + et*128;

    if (t < 128) invb[t] = 1.0f / g_bot[b*SEQ + st*128 + t];

    float acc[4][4][4] = {};
    int a_d4 = (t & 7)*4, a_s = t >> 3;              // A loader: 32 s/pass
    int b_r = t >> 5, b_c = (t & 31)*4;              // B loader: 8 d/pass
    for (int k0 = 0; k0 < DIM; k0 += 32){
        #pragma unroll
        for (int p = 0; p < 4; p++){
            int s = a_s + p*32;
            float4 q4 = *(const float4*)(Qb + (size_t)s*DIM + k0 + a_d4);
            uint4 qa = { to_tf32(phi(q4.x)), to_tf32(phi(q4.y)),
                         to_tf32(phi(q4.z)), to_tf32(phi(q4.w)) };
            *(uint4*)&As[s][a_d4] = qa;
            int row = b_r + p*8;
            float4 kv4 = *(const float4*)(KVb + (size_t)(k0+row)*DIM + b_c);
            uint4 ba = { to_tf32(kv4.x), to_tf32(kv4.y), to_tf32(kv4.z), to_tf32(kv4.w) };
            *(uint4*)&Bs[row][b_c] = ba;
        }
        __syncthreads();
        #pragma unroll
        for (int kk = 0; kk < 32; kk += 8){
            uint32_t af[4][4];
            #pragma unroll
            for (int mi = 0; mi < 4; mi++){
                int m = wm + mi*16;
                af[mi][0] = As[m+gid  ][kk+tig  ];
                af[mi][1] = As[m+gid+8][kk+tig  ];
                af[mi][2] = As[m+gid  ][kk+tig+4];
                af[mi][3] = As[m+gid+8][kk+tig+4];
            }
            #pragma unroll
            for (int ni = 0; ni < 4; ni++){
                int n = wn + ni*8;
                uint32_t b0 = Bs[kk+tig  ][n+gid];
                uint32_t b1 = Bs[kk+tig+4][n+gid];
                #pragma unroll
                for (int mi = 0; mi < 4; mi++) mma8(acc[mi][ni], af[mi], b0, b1);
            }
        }
        __syncthreads();
    }
    float* outp = Out + ((size_t)b*SEQ + st*128)*DIM + et*128;
    #pragma unroll
    for (int mi = 0; mi < 4; mi++)
        #pragma unroll
        for (int ni = 0; ni < 4; ni++){
            int r = wm + mi*16 + gid, c = wn + ni*8 + tig*2;
            float ib0 = invb[r], ib1 = invb[r+8];
            float2 v0 = {acc[mi][ni][0]*ib0, acc[mi][ni][1]*ib0};
            float2 v1 = {acc[mi][ni][2]*ib1, acc[mi][ni][3]*ib1};
            *(float2*)(outp + (size_t)r*DIM + c)     = v0;
            *(float2*)(outp + (size_t)(r+8)*DIM + c) = v1;
        }
}

// ---------------------------------------------------------------------------
extern "C" void kernel_launch(void* const* d_in, const int* in_sizes, int n_in,
                              void* d_out, int out_size){
    const float* Q = (const float*)d_in[0];
    const float* K = (const float*)d_in[1];
    const float* V = (const float*)d_in[2];
    float* Out = (float*)d_out;

    ksum_part_kernel  <<<dim3(16, 8), 256>>>(K);
    ksum_reduce_kernel<<<(BATCH*DIM)/256, 256>>>();
    kv_part_kernel    <<<dim3(4, SPLITK, BATCH), 256>>>(K, V);
    kv_reduce_kernel  <<<(BATCH*DIM*DIM)/(256*4), 256>>>();
    bottom_kernel     <<<(BATCH*SEQ)/8, 256>>>(Q);
    out_kernel        <<<dim3(2, 32, BATCH), 256>>>(Q, Out);
}

// round 5
// speedup vs baseline: 5.8800x; 2.3990x over previous
#include <cuda_runtime.h>
#include <cstdint>

#define BATCH 8
#define SEQ   4096
#define DIM   256
#define SPLITK 8
#define SCHUNK (SEQ/SPLITK)   // 512
#define KC 16                 // k-chunk (double buffered)

// Scratch (no allocs allowed -> __device__ globals)
__device__ float g_KVp[SPLITK*BATCH*DIM*DIM];  // split-K partials [sp][b][d][e]
__device__ float g_KV [BATCH*DIM*DIM];         // KV = phiK^T V   [b][d][e]
__device__ float g_ksp[BATCH*SPLITK*DIM];      // k_sum split partials
__device__ float g_ks [BATCH*DIM];             // k_sum[b][d]

__device__ __forceinline__ float phi(float x){
    // sigmoid(0.6053*x - 4.102) = 1/(1+exp(4.102 - 0.6053*x))
    return 1.0f / (1.0f + __expf(4.102f - 0.6053f * x));
}
__device__ __forceinline__ uint32_t to_tf32(float x){
    uint32_t r; asm("cvt.rna.tf32.f32 %0, %1;" : "=r"(r) : "f"(x)); return r;
}
__device__ __forceinline__ uint32_t f2tf(uint32_t raw){
    return to_tf32(__uint_as_float(raw));
}
__device__ __forceinline__ void mma8(float c[4], const uint32_t a[4],
                                     uint32_t b0, uint32_t b1){
    asm volatile("mma.sync.aligned.m16n8k8.row.col.f32.tf32.tf32.f32 "
        "{%0,%1,%2,%3},{%4,%5,%6,%7},{%8,%9},{%0,%1,%2,%3};"
        : "+f"(c[0]),"+f"(c[1]),"+f"(c[2]),"+f"(c[3])
        : "r"(a[0]),"r"(a[1]),"r"(a[2]),"r"(a[3]),"r"(b0),"r"(b1));
}
__device__ __forceinline__ void cp16(uint32_t dst, const void* src){
    asm volatile("cp.async.ca.shared.global [%0], [%1], 16;" :: "r"(dst), "l"(src));
}
__device__ __forceinline__ void cp_commit(){ asm volatile("cp.async.commit_group;"); }
__device__ __forceinline__ void cp_wait0(){ asm volatile("cp.async.wait_group 0;"); }

// ---------------------------------------------------------------------------
// GEMM 1 (tf32 mma, split-K, pipelined) + fused k_sum partials
// KVp[sp][b][d][e] += phi(K[b][s][d]) * V[b][s][e]
// 128x128 tile, 8 warps (2m x 4n) of 64x32, k-chunk 16, double buffered.
// A = phi(K) as [k][m] (reg-prefetch + phi + STS), B = V raw via cp.async.
// ---------------------------------------------------------------------------
__global__ __launch_bounds__(256,2) void kv_part_kernel(const float* __restrict__ K,
                                                        const float* __restrict__ V){
    __shared__ uint32_t As[2][KC][136];
    __shared__ uint32_t Bs[2][KC][136];
    __shared__ float ksred[8][128];
    int b  = blockIdx.z, sp = blockIdx.y;
    int dt = blockIdx.x >> 1, et = blockIdx.x & 1;
    int t = threadIdx.x, lane = t & 31, w = t >> 5;
    int wm = (w & 1)*64, wn = (w >> 1)*32;
    int gid = lane >> 2, tig = lane & 3;

    const float* Kb = K + ((size_t)b*SEQ + (size_t)sp*SCHUNK)*DIM + dt*128;
    const float* Vb = V + ((size_t)b*SEQ + (size_t)sp*SCHUNK)*DIM + et*128;

    int lr = w, lc = lane*4;   // loader: rows lr, lr+8; 128 floats/row
    float ksum_p[4] = {0.f,0.f,0.f,0.f};
    float4 kreg[2];

    // ---- prologue: chunk 0 ----
    #pragma unroll
    for (int p = 0; p < 2; p++){
        int row = lr + p*8;
        kreg[p] = *(const float4*)(Kb + (size_t)row*DIM + lc);
        cp16((uint32_t)__cvta_generic_to_shared(&Bs[0][row][lc]),
             Vb + (size_t)row*DIM + lc);
    }
    cp_commit();
    #pragma unroll
    for (int p = 0; p < 2; p++){
        int row = lr + p*8;
        float p0=phi(kreg[p].x), p1=phi(kreg[p].y), p2=phi(kreg[p].z), p3=phi(kreg[p].w);
        ksum_p[0]+=p0; ksum_p[1]+=p1; ksum_p[2]+=p2; ksum_p[3]+=p3;
        uint4 u = { to_tf32(p0), to_tf32(p1), to_tf32(p2), to_tf32(p3) };
        *(uint4*)&As[0][row][lc] = u;
    }
    cp_wait0();
    __syncthreads();

    float acc[4][4][4] = {};
    int stage = 0;
    for (int k0 = 0; k0 < SCHUNK; k0 += KC){
        int nxt = stage ^ 1;
        bool hn = (k0 + KC) < SCHUNK;
        if (hn){
            #pragma unroll
            for (int p = 0; p < 2; p++){
                int row = lr + p*8;
                kreg[p] = *(const float4*)(Kb + (size_t)(k0+KC+row)*DIM + lc);
                cp16((uint32_t)__cvta_generic_to_shared(&Bs[nxt][row][lc]),
                     Vb + (size_t)(k0+KC+row)*DIM + lc);
            }
            cp_commit();
        }
        #pragma unroll
        for (int kk = 0; kk < KC; kk += 8){
            uint32_t af[4][4];
            #pragma unroll
            for (int mi = 0; mi < 4; mi++){
                int m = wm + mi*16;
                af[mi][0] = As[stage][kk+tig  ][m+gid  ];
                af[mi][1] = As[stage][kk+tig  ][m+gid+8];
                af[mi][2] = As[stage][kk+tig+4][m+gid  ];
                af[mi][3] = As[stage][kk+tig+4][m+gid+8];
            }
            #pragma unroll
            for (int ni = 0; ni < 4; ni++){
                int n = wn + ni*8;
                uint32_t b0 = f2tf(Bs[stage][kk+tig  ][n+gid]);
                uint32_t b1 = f2tf(Bs[stage][kk+tig+4][n+gid]);
                #pragma unroll
                for (int mi = 0; mi < 4; mi++) mma8(acc[mi][ni], af[mi], b0, b1);
            }
        }
        if (hn){
            #pragma unroll
            for (int p = 0; p < 2; p++){
                int row = lr + p*8;
                float p0=phi(kreg[p].x), p1=phi(kreg[p].y), p2=phi(kreg[p].z), p3=phi(kreg[p].w);
                ksum_p[0]+=p0; ksum_p[1]+=p1; ksum_p[2]+=p2; ksum_p[3]+=p3;
                uint4 u = { to_tf32(p0), to_tf32(p1), to_tf32(p2), to_tf32(p3) };
                *(uint4*)&As[nxt][row][lc] = u;
            }
        }
        cp_wait0();
        __syncthreads();
        stage = nxt;
    }

    // fused k_sum partial: reduce across 8 warps via SMEM (et==0 blocks only write)
    *(float4*)&ksred[w][lc] = make_float4(ksum_p[0], ksum_p[1], ksum_p[2], ksum_p[3]);
    __syncthreads();
    if (et == 0 && t < 128){
        float s = 0.f;
        #pragma unroll
        for (int ww = 0; ww < 8; ww++) s += ksred[ww][t];
        g_ksp[(b*SPLITK + sp)*DIM + dt*128 + t] = s;
    }

    float* outp = g_KVp + (((size_t)sp*BATCH + b)*DIM + dt*128)*DIM + et*128;
    #pragma unroll
    for (int mi = 0; mi < 4; mi++)
        #pragma unroll
        for (int ni = 0; ni < 4; ni++){
            int r = wm + mi*16 + gid, c = wn + ni*8 + tig*2;
            float2 v0 = {acc[mi][ni][0], acc[mi][ni][1]};
            float2 v1 = {acc[mi][ni][2], acc[mi][ni][3]};
            *(float2*)(outp + (size_t)r*DIM + c)     = v0;
            *(float2*)(outp + (size_t)(r+8)*DIM + c) = v1;
        }
}

__global__ __launch_bounds__(256) void ksum_reduce_kernel(){
    int i = blockIdx.x*256 + threadIdx.x;      // [0, BATCH*DIM)
    int b = i / DIM, d = i % DIM;
    float acc = 0.f;
    #pragma unroll
    for (int sp = 0; sp < SPLITK; sp++) acc += g_ksp[(b*SPLITK + sp)*DIM + d];
    g_ks[i] = acc;
}

__global__ __launch_bounds__(256) void kv_reduce_kernel(){
    int i = (blockIdx.x*256 + threadIdx.x)*4;  // float4 over BATCH*DIM*DIM
    float4 acc = {0.f,0.f,0.f,0.f};
    #pragma unroll
    for (int s = 0; s < SPLITK; s++){
        float4 v = *(const float4*)&g_KVp[(size_t)s*BATCH*DIM*DIM + i];
        acc.x += v.x; acc.y += v.y; acc.z += v.z; acc.w += v.w;
    }
    *(float4*)&g_KV[i] = acc;
}

// ---------------------------------------------------------------------------
// GEMM 2 (tf32 mma, pipelined) + fused bottom/normalizer
// Out[b][s][e] = (phi(Q[b][s][:]) . KV[b][:][e]) / (phi(Q[b][s][:]) . k_sum[b])
// 128x128 tile, 8 warps 64x32, k-chunk 16, double buffered.
// A = phi(Q) as [m][k] stride 20 (reg-prefetch + phi + STS), B = KV via cp.async.
// ---------------------------------------------------------------------------
__global__ __launch_bounds__(256,2) void out_kernel(const float* __restrict__ Q,
                                                    float* __restrict__ Out){
    __shared__ uint32_t As[2][128][20];
    __shared__ uint32_t Bs[2][KC][136];
    __shared__ float ks_s[DIM];
    __shared__ float invb[128];
    int b = blockIdx.z, st = blockIdx.y, et = blockIdx.x;
    int t = threadIdx.x, lane = t & 31, w = t >> 5;
    int wm = (w & 1)*64, wn = (w >> 1)*32;
    int gid = lane >> 2, tig = lane & 3;

    const float* Qb  = Q + ((size_t)b*SEQ + st*128)*DIM;
    const float* KVb = g_KV + (size_t)b*DIM*DIM + et*128;

    ks_s[t] = g_ks[b*DIM + t];   // 256 threads cover DIM=256

    int a_s = t >> 2, a_d4 = (t & 3)*4;    // A loader: rows a_s, a_s+64; cols a_d4..+3
    int b_r = w, b_c = lane*4;             // B loader: rows b_r, b_r+8
    float bot_p[2] = {0.f, 0.f};
    float4 qreg[2];

    // ---- prologue: chunk 0 ----
    #pragma unroll
    for (int p = 0; p < 2; p++){
        qreg[p] = *(const float4*)(Qb + (size_t)(a_s + p*64)*DIM + a_d4);
        cp16((uint32_t)__cvta_generic_to_shared(&Bs[0][b_r + p*8][b_c]),
             KVb + (size_t)(b_r + p*8)*DIM + b_c);
    }
    cp_commit();
    __syncthreads();            // ks_s visible before bottom accumulation
    #pragma unroll
    for (int p = 0; p < 2; p++){
        int s = a_s + p*64;
        float p0=phi(qreg[p].x), p1=phi(qreg[p].y), p2=phi(qreg[p].z), p3=phi(qreg[p].w);
        bot_p[p] += p0*ks_s[a_d4] + p1*ks_s[a_d4+1] + p2*ks_s[a_d4+2] + p3*ks_s[a_d4+3];
        uint4 u = { to_tf32(p0), to_tf32(p1), to_tf32(p2), to_tf32(p3) };
        *(uint4*)&As[0][s][a_d4] = u;
    }
    cp_wait0();
    __syncthreads();

    float acc[4][4][4] = {};
    int stage = 0;
    for (int k0 = 0; k0 < DIM; k0 += KC){
        int nxt = stage ^ 1;
        bool hn = (k0 + KC) < DIM;
        if (hn){
            #pragma unroll
            for (int p = 0; p < 2; p++){
                qreg[p] = *(const float4*)(Qb + (size_t)(a_s + p*64)*DIM + k0 + KC + a_d4);
                cp16((uint32_t)__cvta_generic_to_shared(&Bs[nxt][b_r + p*8][b_c]),
                     KVb + (size_t)(k0 + KC + b_r + p*8)*DIM + b_c);
            }
            cp_commit();
        }
        #pragma unroll
        for (int kk = 0; kk < KC; kk += 8){
            uint32_t af[4][4];
            #pragma unroll
            for (int mi = 0; mi < 4; mi++){
                int m = wm + mi*16;
                af[mi][0] = As[stage][m+gid  ][kk+tig  ];
                af[mi][1] = As[stage][m+gid+8][kk+tig  ];
                af[mi][2] = As[stage][m+gid  ][kk+tig+4];
                af[mi][3] = As[stage][m+gid+8][kk+tig+4];
            }
            #pragma unroll
            for (int ni = 0; ni < 4; ni++){
                int n = wn + ni*8;
                uint32_t b0 = f2tf(Bs[stage][kk+tig  ][n+gid]);
                uint32_t b1 = f2tf(Bs[stage][kk+tig+4][n+gid]);
                #pragma unroll
                for (int mi = 0; mi < 4; mi++) mma8(acc[mi][ni], af[mi], b0, b1);
            }
        }
        if (hn){
            #pragma unroll
            for (int p = 0; p < 2; p++){
                int s = a_s + p*64;
                float p0=phi(qreg[p].x), p1=phi(qreg[p].y), p2=phi(qreg[p].z), p3=phi(qreg[p].w);
                bot_p[p] += p0*ks_s[k0+KC+a_d4] + p1*ks_s[k0+KC+a_d4+1]
                          + p2*ks_s[k0+KC+a_d4+2] + p3*ks_s[k0+KC+a_d4+3];
                uint4 u = { to_tf32(p0), to_tf32(p1), to_tf32(p2), to_tf32(p3) };
                *(uint4*)&As[nxt][s][a_d4] = u;
            }
        }
        cp_wait0();
        __syncthreads();
        stage = nxt;
    }

    // fused bottom: reduce over the 4 lanes sharing each row
    #pragma unroll
    for (int p = 0; p < 2; p++){
        bot_p[p] += __shfl_xor_sync(0xffffffffu, bot_p[p], 1);
        bot_p[p] += __shfl_xor_sync(0xffffffffu, bot_p[p], 2);
    }
    if ((t & 3) == 0){
        invb[a_s]      = 1.0f / bot_p[0];
        invb[a_s + 64] = 1.0f / bot_p[1];
    }
    __syncthreads();

    float* outp = Out + ((size_t)b*SEQ + st*128)*DIM + et*128;
    #pragma unroll
    for (int mi = 0; mi < 4; mi++)
        #pragma unroll
        for (int ni = 0; ni < 4; ni++){
            int r = wm + mi*16 + gid, c = wn + ni*8 + tig*2;
            float ib0 = invb[r], ib1 = invb[r+8];
            float2 v0 = {acc[mi][ni][0]*ib0, acc[mi][ni][1]*ib0};
            float2 v1 = {acc[mi][ni][2]*ib1, acc[mi][ni][3]*ib1};
            *(float2*)(outp + (size_t)r*DIM + c)     = v0;
            *(float2*)(outp + (size_t)(r+8)*DIM + c) = v1;
        }
}

// ---------------------------------------------------------------------------
extern "C" void kernel_launch(void* const* d_in, const int* in_sizes, int n_in,
                              void* d_out, int out_size){
    const float* Q = (const float*)d_in[0];
    const float* K = (const float*)d_in[1];
    const float* V = (const float*)d_in[2];
    float* Out = (float*)d_out;

    kv_part_kernel    <<<dim3(4, SPLITK, BATCH), 256>>>(K, V);
    ksum_reduce_kernel<<<(BATCH*DIM)/256, 256>>>();
    kv_reduce_kernel  <<<(BATCH*DIM*DIM)/(256*4), 256>>>();
    out_kernel        <<<dim3(2, 32, BATCH), 256>>>(Q, Out);
}